// round 16
// baseline (speedup 1.0000x reference)
#include <cuda_runtime.h>

// Shapes: x, y : (16, 64, 256, 256) fp32 ; out : (16, 256, 256) fp32
// out[b,i] = sum_c x[b,c,i] * w[b,c],  w[b,c] = sum_j y[b,c,j] / (65536*4194304)
//
// FINAL (exact R10-winner build; best wall 80.58us, best kernel 79.9us).
// R14's 128-thread/72-reg experiment confirmed the 6.7 TB/s plateau is the
// HBM device-efficiency wall, not MLP — varying aggregate in-flight loads
// +/-30% left bandwidth unchanged.
//
// Fused single kernel, 1024 blocks x 256 threads, all resident in one wave
// (launch_bounds(256,7) -> 7 x 148 = 1036 >= 1024 : required, the per-batch
// barrier deadlocks if any block of a batch is non-resident).
//
// Barrier: monotonic per-batch ticket counter (NEVER reset). ticket/64 gives
// the round; wait until counter >= (round+1)*64. Single location, total order
// from atomicAdd, stale reads only under-read -> deadlock-free by construction.
// Counter value differs across graph replays but output does not.
//
// Validated-by-measurement design ledger (kernel-internal deltas):
//  + fusion vs two kernels:                ~ +1.0 us
//  + own-plane pre-accumulation overlapping the barrier wait: ~ +0.6 us
//  + branch-free phase-B sweep:            ~ +0.6 us
//  + 63-iter index-remap (no own-plane re-read, -4MB traffic): ~ +0.6 us
//  - grid=256 "long burst" variant:        -16 us  (occupancy/MLP collapse)
//  - additive pointer stepping:            -1.5 us (serialized address chain)
//  = unroll 9 / 128-thr 72-reg / cache-hint variants: neutral (HBM wall)
//
// Converged: kernel 80.6 +/- 0.7 us @ 6.6-6.8 TB/s (84-85% DRAM) = ~96% of
// the 76.2us floor for the minimal 516MB of traffic at this chip's achieved
// streaming ceiling. Remaining gap is ramp + barrier transition + wave tail,
// all below run-to-run noise.

#define NB 16
#define NC 64
#define HW 65536               // 256*256
#define HW4 (HW / 4)           // 16384 float4 per (b,c) plane
#define SCALE (1.0f / (65536.0f * 4194304.0f))  // exact: 2^-38

__device__ float g_w[NB * NC];
__device__ unsigned int g_cnt[NB];     // monotonic ticket counter (never reset)

__global__ void __launch_bounds__(256, 7)
fused_kernel(const float4* __restrict__ x4,
             const float4* __restrict__ y4,
             float4* __restrict__ out4) {
    const int blk = blockIdx.x;            // 0..1023 == plane index b*64+c
    const int b = blk >> 6;                // batch
    const int own_c = blk & 63;            // this block's channel / output chunk
    const int t = threadIdx.x;

    __shared__ float w[NC];
    __shared__ float red[8];
    __shared__ unsigned int s_target;

    // ---------------- Phase A: reduce y-plane blk ----------------
    {
        const float4* p = y4 + (size_t)blk * HW4;
        float s = 0.0f;
        #pragma unroll 8
        for (int k = 0; k < 64; ++k) {
            float4 v = __ldcs(&p[t + k * 256]);   // y read exactly once: stream
            s += (v.x + v.y) + (v.z + v.w);
        }
        #pragma unroll
        for (int o = 16; o > 0; o >>= 1)
            s += __shfl_xor_sync(0xFFFFFFFF, s, o);
        if ((t & 31) == 0) red[t >> 5] = s;
    }
    __syncthreads();

    // ------------- Publish w_own + barrier ARRIVE (ticket, no wait) --------
    float w_own = 0.0f;
    if (t == 0) {
        float tot = 0.0f;
        #pragma unroll
        for (int i = 0; i < 8; ++i) tot += red[i];
        const float wo = tot * SCALE;
        g_w[blk] = wo;                                // publish for batch peers
        red[0] = wo;                                  // local broadcast slot
        __threadfence();                              // release g_w[blk]
        unsigned ticket = atomicAdd(&g_cnt[b], 1u);   // totally ordered arrive
        s_target = ((ticket >> 6) + 1u) << 6;         // end of this round
    }
    __syncthreads();
    w_own = red[0];

    // ------- Phase B part 1: own plane pre-accumulation (overlaps wait) ----
    const float4* pxb = x4 + (size_t)b * NC * HW4 + own_c * 256 + t;
    float4 acc;
    {
        float4 v = __ldcs(pxb + (size_t)own_c * HW4); // own plane read ONCE
        acc.x = v.x * w_own;
        acc.y = v.y * w_own;
        acc.z = v.z * w_own;
        acc.w = v.w * w_own;
    }

    // ---------------- Barrier WAIT (overlapped by the loads above) ---------
    if (t == 0) {
        const unsigned target = s_target;
        while (*(volatile unsigned*)&g_cnt[b] < target)
            __nanosleep(64);
        __threadfence();                              // acquire before g_w reads
    }
    __syncthreads();
    if (t < NC) w[t] = __ldcg(&g_w[b * NC + t]);      // L2-coherent reload
    __syncthreads();

    // ------- Phase B part 2: 63 planes, branch-free index remap ------------
    // c = k + (k >= own_c) visits 0..63 except own_c; per-iteration cost is
    // one ISETP+IADD (ALU ~7% busy), addresses independent -> batching kept.
    #pragma unroll 7
    for (int k = 0; k < NC - 1; ++k) {
        const int c = k + (int)(k >= own_c);
        float4 v = __ldcs(pxb + (size_t)c * HW4);     // x read exactly once
        const float wc = w[c];
        acc.x += v.x * wc;
        acc.y += v.y * wc;
        acc.z += v.z * wc;
        acc.w += v.w * wc;
    }

    out4[(size_t)blk * 256 + t] = acc;
}

extern "C" void kernel_launch(void* const* d_in, const int* in_sizes, int n_in,
                              void* d_out, int out_size) {
    const float4* x4 = (const float4*)d_in[0];
    const float4* y4 = (const float4*)d_in[1];
    float4* out4 = (float4*)d_out;

    fused_kernel<<<NB * NC, 256>>>(x4, y4, out4);
}

// round 17
// speedup vs baseline: 1.0043x; 1.0043x over previous
#include <cuda_runtime.h>

// Shapes: x, y : (16, 64, 256, 256) fp32 ; out : (16, 256, 256) fp32
// out[b,i] = sum_c x[b,c,i] * w[b,c],  w[b,c] = sum_j y[b,c,j] / (65536*4194304)
//
// FINAL (exact R10-winner build; best wall 80.58us, best kernel 79.9us).
// R14's 128-thread/72-reg experiment confirmed the 6.7 TB/s plateau is the
// HBM device-efficiency wall, not MLP — varying aggregate in-flight loads
// +/-30% left bandwidth unchanged.
//
// Fused single kernel, 1024 blocks x 256 threads, all resident in one wave
// (launch_bounds(256,7) -> 7 x 148 = 1036 >= 1024 : required, the per-batch
// barrier deadlocks if any block of a batch is non-resident).
//
// Barrier: monotonic per-batch ticket counter (NEVER reset). ticket/64 gives
// the round; wait until counter >= (round+1)*64. Single location, total order
// from atomicAdd, stale reads only under-read -> deadlock-free by construction.
// Counter value differs across graph replays but output does not.
//
// Validated-by-measurement design ledger (kernel-internal deltas):
//  + fusion vs two kernels:                ~ +1.0 us
//  + own-plane pre-accumulation overlapping the barrier wait: ~ +0.6 us
//  + branch-free phase-B sweep:            ~ +0.6 us
//  + 63-iter index-remap (no own-plane re-read, -4MB traffic): ~ +0.6 us
//  - grid=256 "long burst" variant:        -16 us  (occupancy/MLP collapse)
//  - additive pointer stepping:            -1.5 us (serialized address chain)
//  = unroll 9 / 128-thr 72-reg / cache-hint variants: neutral (HBM wall)
//
// Converged over 8 runs: kernel 80.6 +/- 0.7 us @ 6.6-6.8 TB/s (84-85% DRAM)
// = ~96% of the 76.2us floor for the minimal 516MB of traffic at this chip's
// achieved streaming ceiling. Remaining gap is ramp + barrier transition +
// wave tail, all below run-to-run noise.

#define NB 16
#define NC 64
#define HW 65536               // 256*256
#define HW4 (HW / 4)           // 16384 float4 per (b,c) plane
#define SCALE (1.0f / (65536.0f * 4194304.0f))  // exact: 2^-38

__device__ float g_w[NB * NC];
__device__ unsigned int g_cnt[NB];     // monotonic ticket counter (never reset)

__global__ void __launch_bounds__(256, 7)
fused_kernel(const float4* __restrict__ x4,
             const float4* __restrict__ y4,
             float4* __restrict__ out4) {
    const int blk = blockIdx.x;            // 0..1023 == plane index b*64+c
    const int b = blk >> 6;                // batch
    const int own_c = blk & 63;            // this block's channel / output chunk
    const int t = threadIdx.x;

    __shared__ float w[NC];
    __shared__ float red[8];
    __shared__ unsigned int s_target;

    // ---------------- Phase A: reduce y-plane blk ----------------
    {
        const float4* p = y4 + (size_t)blk * HW4;
        float s = 0.0f;
        #pragma unroll 8
        for (int k = 0; k < 64; ++k) {
            float4 v = __ldcs(&p[t + k * 256]);   // y read exactly once: stream
            s += (v.x + v.y) + (v.z + v.w);
        }
        #pragma unroll
        for (int o = 16; o > 0; o >>= 1)
            s += __shfl_xor_sync(0xFFFFFFFF, s, o);
        if ((t & 31) == 0) red[t >> 5] = s;
    }
    __syncthreads();

    // ------------- Publish w_own + barrier ARRIVE (ticket, no wait) --------
    float w_own = 0.0f;
    if (t == 0) {
        float tot = 0.0f;
        #pragma unroll
        for (int i = 0; i < 8; ++i) tot += red[i];
        const float wo = tot * SCALE;
        g_w[blk] = wo;                                // publish for batch peers
        red[0] = wo;                                  // local broadcast slot
        __threadfence();                              // release g_w[blk]
        unsigned ticket = atomicAdd(&g_cnt[b], 1u);   // totally ordered arrive
        s_target = ((ticket >> 6) + 1u) << 6;         // end of this round
    }
    __syncthreads();
    w_own = red[0];

    // ------- Phase B part 1: own plane pre-accumulation (overlaps wait) ----
    const float4* pxb = x4 + (size_t)b * NC * HW4 + own_c * 256 + t;
    float4 acc;
    {
        float4 v = __ldcs(pxb + (size_t)own_c * HW4); // own plane read ONCE
        acc.x = v.x * w_own;
        acc.y = v.y * w_own;
        acc.z = v.z * w_own;
        acc.w = v.w * w_own;
    }

    // ---------------- Barrier WAIT (overlapped by the loads above) ---------
    if (t == 0) {
        const unsigned target = s_target;
        while (*(volatile unsigned*)&g_cnt[b] < target)
            __nanosleep(64);
        __threadfence();                              // acquire before g_w reads
    }
    __syncthreads();
    if (t < NC) w[t] = __ldcg(&g_w[b * NC + t]);      // L2-coherent reload
    __syncthreads();

    // ------- Phase B part 2: 63 planes, branch-free index remap ------------
    // c = k + (k >= own_c) visits 0..63 except own_c; per-iteration cost is
    // one ISETP+IADD (ALU ~7% busy), addresses independent -> batching kept.
    #pragma unroll 7
    for (int k = 0; k < NC - 1; ++k) {
        const int c = k + (int)(k >= own_c);
        float4 v = __ldcs(pxb + (size_t)c * HW4);     // x read exactly once
        const float wc = w[c];
        acc.x += v.x * wc;
        acc.y += v.y * wc;
        acc.z += v.z * wc;
        acc.w += v.w * wc;
    }

    out4[(size_t)blk * 256 + t] = acc;
}

extern "C" void kernel_launch(void* const* d_in, const int* in_sizes, int n_in,
                              void* d_out, int out_size) {
    const float4* x4 = (const float4*)d_in[0];
    const float4* y4 = (const float4*)d_in[1];
    float4* out4 = (float4*)d_out;

    fused_kernel<<<NB * NC, 256>>>(x4, y4, out4);
}